// round 2
// baseline (speedup 1.0000x reference)
#include <cuda_runtime.h>
#include <math.h>

#define D 256
#define HH 512
#define MT 32            // rows per CTA
#define NTHREADS 512
#define KXS 1032         // x-tile row stride (floats), [m][k] layout
#define HS  520          // h-tile row stride (floats), [m][k] layout
#define MAX_NODES 65536
#define MAX_LVL 16384

// Scratch (static __device__ — no runtime allocation)
__device__ float g_embeds[MAX_NODES * D];
__device__ int   g_list[6][MAX_LVL];
__device__ int   g_cnt[6];
// Transposed weights [c][k]
__device__ float g_WT1b[HH * 768];
__device__ float g_WT1t[HH * 1024];
__device__ float g_WT2b[D * HH];
__device__ float g_WT2t[D * HH];

// ---------------- helpers ----------------
__device__ __forceinline__ void fma2(unsigned long long &acc, unsigned long long w, unsigned long long x) {
    asm("fma.rn.f32x2 %0, %1, %2, %0;" : "+l"(acc) : "l"(w), "l"(x));
}
__device__ __forceinline__ float2 unpack2(unsigned long long v) {
    float lo, hi;
    asm("mov.b64 {%0, %1}, %2;" : "=f"(lo), "=f"(hi) : "l"(v));
    return make_float2(lo, hi);
}
__device__ __forceinline__ float gelu_exact(float x) {
    return 0.5f * x * (1.0f + erff(x * 0.70710678118654752440f));
}

// ---------------- init ----------------
__global__ void init_embeds_kernel(const int* __restrict__ comp_ids,
                                   const float* __restrict__ comp_table) {
    int node = blockIdx.x;
    int c = threadIdx.x;
    g_embeds[node * D + c] = comp_table[comp_ids[node] * D + c];
}

__global__ void reset_kernel() {
    if (threadIdx.x < 6) g_cnt[threadIdx.x] = 0;
}

__global__ void compact_kernel(const int* __restrict__ lvl2, int n2,
                               const int* __restrict__ lvl1, int n1,
                               const int* __restrict__ lvl0, int n0,
                               const int* __restrict__ third) {
    int i = blockIdx.x * blockDim.x + threadIdx.x;
    int lvl, j;
    const int* idx;
    if (i < n2)               { lvl = 0; j = i;            idx = lvl2; }
    else if (i < n2 + n1)     { lvl = 1; j = i - n2;       idx = lvl1; }
    else if (i < n2 + n1 + n0){ lvl = 2; j = i - n2 - n1;  idx = lvl0; }
    else return;
    int node = idx[j];
    bool tern = (third[node] >= 0);
    int slot = lvl * 2 + (tern ? 0 : 1);
    int pos = atomicAdd(&g_cnt[slot], 1);
    g_list[slot][pos] = j;
}

// ---------------- weight transpose: in [K][C] -> out [C][K] ----------------
__global__ void transpose_kernel(const float* __restrict__ in, float* __restrict__ out,
                                 int K, int C) {
    __shared__ float tile[32][33];
    int c0 = blockIdx.x * 32, k0 = blockIdx.y * 32;
    int tx = threadIdx.x, ty = threadIdx.y;   // 32 x 8
    #pragma unroll
    for (int r = 0; r < 32; r += 8)
        tile[ty + r][tx] = in[(k0 + ty + r) * C + c0 + tx];
    __syncthreads();
    #pragma unroll
    for (int r = 0; r < 32; r += 8)
        out[(c0 + ty + r) * K + k0 + tx] = tile[tx][ty + r];
}

// ---------------- fused level kernel ----------------
#define SMEM_FLOATS (256 + MT * KXS + MT * HS)
#define SMEM_BYTES  (SMEM_FLOATS * 4)

__global__ __launch_bounds__(NTHREADS, 1)
void level_kernel(int nbt, int lvl_slot,
                  const int* __restrict__ lvl_idx,
                  const int* __restrict__ lc, const int* __restrict__ rc,
                  const int* __restrict__ tcld,
                  const int* __restrict__ opids,
                  const float* __restrict__ op_table,
                  const float* __restrict__ b1b, const float* __restrict__ b2b,
                  const float* __restrict__ b1t, const float* __restrict__ b2t,
                  const float* __restrict__ gma, const float* __restrict__ bta,
                  float* __restrict__ final_out) {
    extern __shared__ float smem[];
    int* meta = (int*)smem;                 // [0..31]=node, [32..63]=i, [64..95]=valid
    float* xs = smem + 256;                 // [m][k], stride KXS
    float* hs = xs + MT * KXS;              // [m][k], stride HS (reused as z buffer)

    bool tern = (blockIdx.x < nbt);
    int slot = lvl_slot * 2 + (tern ? 0 : 1);
    int cnt = g_cnt[slot];
    int blk = tern ? blockIdx.x : (blockIdx.x - nbt);
    int base = blk * MT;
    if (base >= cnt) return;

    const int* rows = g_list[slot];
    const int K1 = tern ? 1024 : 768;
    const float* WT1 = tern ? g_WT1t : g_WT1b;
    const float* B1  = tern ? b1t : b1b;
    const float* WT2 = tern ? g_WT2t : g_WT2b;
    const float* B2  = tern ? b2t : b2b;

    int t = threadIdx.x;

    // ---- gather x tile: xs[m][k] ----
    {
        int m = t >> 4, q = t & 15;
        int rr = min(base + m, cnt - 1);
        int i = rows[rr];
        int node = lvl_idx[i];
        if (q == 0) {
            meta[m] = node;
            meta[32 + m] = i;
            meta[64 + m] = (base + m < cnt) ? 1 : 0;
        }
        int ln = lc[node], rn = rc[node];
        const float* src0 = op_table + opids[node] * D;
        const float* src1 = g_embeds + (size_t)ln * D;
        const float* src2 = g_embeds + (size_t)rn * D;
        const float* src3 = tern ? (g_embeds + (size_t)tcld[node] * D) : src1;
        const float* srcs[4] = {src0, src1, src2, src3};
        float4* dstrow = (float4*)(xs + m * KXS);
        int nseg = tern ? 4 : 3;
        for (int s = 0; s < nseg; s++) {
            const float4* sp = (const float4*)srcs[s];
            #pragma unroll
            for (int kk = q; kk < 64; kk += 16)
                dstrow[s * 64 + kk] = sp[kk];
        }
    }
    __syncthreads();

    int cg = t & 127, rg = t >> 7;

    // ---- GEMM1: h = gelu(x @ W1 + b1); per thread 4 cols x 8 rows, K-packed ----
    {
        int c0 = cg * 4, r0 = rg * 8;
        unsigned long long acc[32];
        #pragma unroll
        for (int z = 0; z < 32; z++) acc[z] = 0ULL;

        const float* w0 = WT1 + (size_t)c0 * K1;
        const float* xr = xs + r0 * KXS;
        int n4 = K1 >> 2;

        ulonglong2 wn0 = *(const ulonglong2*)(w0);
        ulonglong2 wn1 = *(const ulonglong2*)(w0 + K1);
        ulonglong2 wn2 = *(const ulonglong2*)(w0 + 2 * K1);
        ulonglong2 wn3 = *(const ulonglong2*)(w0 + 3 * K1);

        #pragma unroll 2
        for (int j = 0; j < n4; j++) {
            ulonglong2 wc0 = wn0, wc1 = wn1, wc2 = wn2, wc3 = wn3;
            if (j + 1 < n4) {
                const float* wp = w0 + 4 * (j + 1);
                wn0 = *(const ulonglong2*)(wp);
                wn1 = *(const ulonglong2*)(wp + K1);
                wn2 = *(const ulonglong2*)(wp + 2 * K1);
                wn3 = *(const ulonglong2*)(wp + 3 * K1);
            }
            const float* xb = xr + 4 * j;
            // rows 0..3
            {
                ulonglong2 x0 = *(const ulonglong2*)(xb);
                ulonglong2 x1 = *(const ulonglong2*)(xb + KXS);
                ulonglong2 x2 = *(const ulonglong2*)(xb + 2 * KXS);
                ulonglong2 x3 = *(const ulonglong2*)(xb + 3 * KXS);
                fma2(acc[0],  wc0.x, x0.x); fma2(acc[0],  wc0.y, x0.y);
                fma2(acc[1],  wc0.x, x1.x); fma2(acc[1],  wc0.y, x1.y);
                fma2(acc[2],  wc0.x, x2.x); fma2(acc[2],  wc0.y, x2.y);
                fma2(acc[3],  wc0.x, x3.x); fma2(acc[3],  wc0.y, x3.y);
                fma2(acc[8],  wc1.x, x0.x); fma2(acc[8],  wc1.y, x0.y);
                fma2(acc[9],  wc1.x, x1.x); fma2(acc[9],  wc1.y, x1.y);
                fma2(acc[10], wc1.x, x2.x); fma2(acc[10], wc1.y, x2.y);
                fma2(acc[11], wc1.x, x3.x); fma2(acc[11], wc1.y, x3.y);
                fma2(acc[16], wc2.x, x0.x); fma2(acc[16], wc2.y, x0.y);
                fma2(acc[17], wc2.x, x1.x); fma2(acc[17], wc2.y, x1.y);
                fma2(acc[18], wc2.x, x2.x); fma2(acc[18], wc2.y, x2.y);
                fma2(acc[19], wc2.x, x3.x); fma2(acc[19], wc2.y, x3.y);
                fma2(acc[24], wc3.x, x0.x); fma2(acc[24], wc3.y, x0.y);
                fma2(acc[25], wc3.x, x1.x); fma2(acc[25], wc3.y, x1.y);
                fma2(acc[26], wc3.x, x2.x); fma2(acc[26], wc3.y, x2.y);
                fma2(acc[27], wc3.x, x3.x); fma2(acc[27], wc3.y, x3.y);
            }
            // rows 4..7
            {
                ulonglong2 x0 = *(const ulonglong2*)(xb + 4 * KXS);
                ulonglong2 x1 = *(const ulonglong2*)(xb + 5 * KXS);
                ulonglong2 x2 = *(const ulonglong2*)(xb + 6 * KXS);
                ulonglong2 x3 = *(const ulonglong2*)(xb + 7 * KXS);
                fma2(acc[4],  wc0.x, x0.x); fma2(acc[4],  wc0.y, x0.y);
                fma2(acc[5],  wc0.x, x1.x); fma2(acc[5],  wc0.y, x1.y);
                fma2(acc[6],  wc0.x, x2.x); fma2(acc[6],  wc0.y, x2.y);
                fma2(acc[7],  wc0.x, x3.x); fma2(acc[7],  wc0.y, x3.y);
                fma2(acc[12], wc1.x, x0.x); fma2(acc[12], wc1.y, x0.y);
                fma2(acc[13], wc1.x, x1.x); fma2(acc[13], wc1.y, x1.y);
                fma2(acc[14], wc1.x, x2.x); fma2(acc[14], wc1.y, x2.y);
                fma2(acc[15], wc1.x, x3.x); fma2(acc[15], wc1.y, x3.y);
                fma2(acc[20], wc2.x, x0.x); fma2(acc[20], wc2.y, x0.y);
                fma2(acc[21], wc2.x, x1.x); fma2(acc[21], wc2.y, x1.y);
                fma2(acc[22], wc2.x, x2.x); fma2(acc[22], wc2.y, x2.y);
                fma2(acc[23], wc2.x, x3.x); fma2(acc[23], wc2.y, x3.y);
                fma2(acc[28], wc3.x, x0.x); fma2(acc[28], wc3.y, x0.y);
                fma2(acc[29], wc3.x, x1.x); fma2(acc[29], wc3.y, x1.y);
                fma2(acc[30], wc3.x, x2.x); fma2(acc[30], wc3.y, x2.y);
                fma2(acc[31], wc3.x, x3.x); fma2(acc[31], wc3.y, x3.y);
            }
        }

        // epilogue: horizontal add + bias + gelu -> hs[m][c]
        float bias0 = B1[c0], bias1 = B1[c0 + 1], bias2 = B1[c0 + 2], bias3 = B1[c0 + 3];
        #pragma unroll
        for (int ri = 0; ri < 8; ri++) {
            float2 f0 = unpack2(acc[ri]);
            float2 f1 = unpack2(acc[8 + ri]);
            float2 f2 = unpack2(acc[16 + ri]);
            float2 f3 = unpack2(acc[24 + ri]);
            float4 v;
            v.x = gelu_exact(f0.x + f0.y + bias0);
            v.y = gelu_exact(f1.x + f1.y + bias1);
            v.z = gelu_exact(f2.x + f2.y + bias2);
            v.w = gelu_exact(f3.x + f3.y + bias3);
            *(float4*)(hs + (r0 + ri) * HS + c0) = v;
        }
    }
    __syncthreads();

    // ---- GEMM2: y = h @ W2 + b2; per thread 2 cols x 8 rows, K-packed ----
    {
        int c0 = cg * 2, r0 = rg * 8;
        unsigned long long acc[16];
        #pragma unroll
        for (int z = 0; z < 16; z++) acc[z] = 0ULL;

        const float* w0 = WT2 + (size_t)c0 * HH;
        const float* hr = hs + r0 * HS;
        const int n4 = HH >> 2;   // 128

        ulonglong2 wn0 = *(const ulonglong2*)(w0);
        ulonglong2 wn1 = *(const ulonglong2*)(w0 + HH);

        #pragma unroll 2
        for (int j = 0; j < n4; j++) {
            ulonglong2 wc0 = wn0, wc1 = wn1;
            if (j + 1 < n4) {
                const float* wp = w0 + 4 * (j + 1);
                wn0 = *(const ulonglong2*)(wp);
                wn1 = *(const ulonglong2*)(wp + HH);
            }
            const float* hb = hr + 4 * j;
            ulonglong2 x0 = *(const ulonglong2*)(hb);
            ulonglong2 x1 = *(const ulonglong2*)(hb + HS);
            ulonglong2 x2 = *(const ulonglong2*)(hb + 2 * HS);
            ulonglong2 x3 = *(const ulonglong2*)(hb + 3 * HS);
            ulonglong2 x4 = *(const ulonglong2*)(hb + 4 * HS);
            ulonglong2 x5 = *(const ulonglong2*)(hb + 5 * HS);
            ulonglong2 x6 = *(const ulonglong2*)(hb + 6 * HS);
            ulonglong2 x7 = *(const ulonglong2*)(hb + 7 * HS);
            fma2(acc[0],  wc0.x, x0.x); fma2(acc[0],  wc0.y, x0.y);
            fma2(acc[1],  wc0.x, x1.x); fma2(acc[1],  wc0.y, x1.y);
            fma2(acc[2],  wc0.x, x2.x); fma2(acc[2],  wc0.y, x2.y);
            fma2(acc[3],  wc0.x, x3.x); fma2(acc[3],  wc0.y, x3.y);
            fma2(acc[4],  wc0.x, x4.x); fma2(acc[4],  wc0.y, x4.y);
            fma2(acc[5],  wc0.x, x5.x); fma2(acc[5],  wc0.y, x5.y);
            fma2(acc[6],  wc0.x, x6.x); fma2(acc[6],  wc0.y, x6.y);
            fma2(acc[7],  wc0.x, x7.x); fma2(acc[7],  wc0.y, x7.y);
            fma2(acc[8],  wc1.x, x0.x); fma2(acc[8],  wc1.y, x0.y);
            fma2(acc[9],  wc1.x, x1.x); fma2(acc[9],  wc1.y, x1.y);
            fma2(acc[10], wc1.x, x2.x); fma2(acc[10], wc1.y, x2.y);
            fma2(acc[11], wc1.x, x3.x); fma2(acc[11], wc1.y, x3.y);
            fma2(acc[12], wc1.x, x4.x); fma2(acc[12], wc1.y, x4.y);
            fma2(acc[13], wc1.x, x5.x); fma2(acc[13], wc1.y, x5.y);
            fma2(acc[14], wc1.x, x6.x); fma2(acc[14], wc1.y, x6.y);
            fma2(acc[15], wc1.x, x7.x); fma2(acc[15], wc1.y, x7.y);
        }
        __syncthreads();   // all GEMM2 reads of hs done before z overwrite

        // residual -> z into hs[m][0..255]
        float bias0 = B2[c0], bias1 = B2[c0 + 1];
        #pragma unroll
        for (int ri = 0; ri < 8; ri++) {
            int m = r0 + ri;
            float2 f0 = unpack2(acc[ri]);
            float2 f1 = unpack2(acc[8 + ri]);
            float y0 = f0.x + f0.y + bias0;
            float y1 = f1.x + f1.y + bias1;
            float2 le = *(const float2*)(xs + m * KXS + 256 + c0);
            float2 re = *(const float2*)(xs + m * KXS + 512 + c0);
            float2 zv;
            if (tern) {
                float2 te = *(const float2*)(xs + m * KXS + 768 + c0);
                zv.x = y0 + (le.x + re.x + te.x) * (1.0f / 3.0f);
                zv.y = y1 + (le.y + re.y + te.y) * (1.0f / 3.0f);
            } else {
                zv.x = y0 + le.x + re.x;
                zv.y = y1 + le.y + re.y;
            }
            *(float2*)(hs + m * HS + c0) = zv;
        }
    }
    __syncthreads();

    // ---- LayerNorm + write out (16 warps x 2 rows) ----
    {
        int wid = t >> 5, lane = t & 31;
        #pragma unroll
        for (int mi = 0; mi < 2; mi++) {
            int m = wid * 2 + mi;
            float v[8];
            float s = 0.0f, s2 = 0.0f;
            #pragma unroll
            for (int j = 0; j < 8; j++) {
                int c = lane + 32 * j;
                v[j] = hs[m * HS + c];
                s += v[j];
                s2 += v[j] * v[j];
            }
            #pragma unroll
            for (int off = 16; off > 0; off >>= 1) {
                s  += __shfl_xor_sync(0xFFFFFFFFu, s, off);
                s2 += __shfl_xor_sync(0xFFFFFFFFu, s2, off);
            }
            float mu = s * (1.0f / 256.0f);
            float var = s2 * (1.0f / 256.0f) - mu * mu;
            float rs = rsqrtf(var + 1e-5f);
            if (meta[64 + m]) {
                int node = meta[m];
                int i = meta[32 + m];
                float* outp = final_out ? (final_out + (size_t)i * D)
                                        : (g_embeds + (size_t)node * D);
                #pragma unroll
                for (int j = 0; j < 8; j++) {
                    int c = lane + 32 * j;
                    outp[c] = (v[j] - mu) * rs * gma[c] + bta[c];
                }
            }
        }
    }
}

// ---------------- launcher ----------------
extern "C" void kernel_launch(void* const* d_in, const int* in_sizes, int n_in,
                              void* d_out, int out_size) {
    const int*   comp_ids   = (const int*)d_in[0];
    const int*   op_ids     = (const int*)d_in[1];
    const int*   lc         = (const int*)d_in[2];
    const int*   rc         = (const int*)d_in[3];
    const int*   tc         = (const int*)d_in[4];
    const int*   l2         = (const int*)d_in[5];
    const int*   l1         = (const int*)d_in[6];
    const int*   l0         = (const int*)d_in[7];
    const float* comp_table = (const float*)d_in[8];
    const float* op_table   = (const float*)d_in[9];
    const float* W1b        = (const float*)d_in[10];
    const float* b1b        = (const float*)d_in[11];
    const float* W2b        = (const float*)d_in[12];
    const float* b2b        = (const float*)d_in[13];
    const float* W1t        = (const float*)d_in[14];
    const float* b1t        = (const float*)d_in[15];
    const float* W2t        = (const float*)d_in[16];
    const float* b2t        = (const float*)d_in[17];
    const float* gma        = (const float*)d_in[18];
    const float* bta        = (const float*)d_in[19];

    int n_nodes = in_sizes[0];
    int n2 = in_sizes[5], n1 = in_sizes[6], n0 = in_sizes[7];

    cudaFuncSetAttribute(level_kernel, cudaFuncAttributeMaxDynamicSharedMemorySize,
                         SMEM_BYTES);

    // weight transposes into [c][k] scratch
    float* wt1b; cudaGetSymbolAddress((void**)&wt1b, g_WT1b);
    float* wt1t; cudaGetSymbolAddress((void**)&wt1t, g_WT1t);
    float* wt2b; cudaGetSymbolAddress((void**)&wt2b, g_WT2b);
    float* wt2t; cudaGetSymbolAddress((void**)&wt2t, g_WT2t);
    dim3 tb(32, 8);
    transpose_kernel<<<dim3(HH / 32, 768 / 32), tb>>>(W1b, wt1b, 768, HH);
    transpose_kernel<<<dim3(HH / 32, 1024 / 32), tb>>>(W1t, wt1t, 1024, HH);
    transpose_kernel<<<dim3(D / 32, HH / 32), tb>>>(W2b, wt2b, HH, D);
    transpose_kernel<<<dim3(D / 32, HH / 32), tb>>>(W2t, wt2t, HH, D);

    init_embeds_kernel<<<n_nodes, D>>>(comp_ids, comp_table);
    reset_kernel<<<1, 32>>>();
    int tot = n2 + n1 + n0;
    compact_kernel<<<(tot + 255) / 256, 256>>>(l2, n2, l1, n1, l0, n0, tc);

    int nb2 = (n2 + MT - 1) / MT;
    level_kernel<<<2 * nb2, NTHREADS, SMEM_BYTES>>>(
        nb2, 0, l2, lc, rc, tc, op_ids, op_table,
        b1b, b2b, b1t, b2t, gma, bta, nullptr);

    int nb1 = (n1 + MT - 1) / MT;
    level_kernel<<<2 * nb1, NTHREADS, SMEM_BYTES>>>(
        nb1, 1, l1, lc, rc, tc, op_ids, op_table,
        b1b, b2b, b1t, b2t, gma, bta, nullptr);

    int nb0 = (n0 + MT - 1) / MT;
    level_kernel<<<2 * nb0, NTHREADS, SMEM_BYTES>>>(
        nb0, 2, l0, lc, rc, tc, op_ids, op_table,
        b1b, b2b, b1t, b2t, gma, bta, (float*)d_out);
}

// round 4
// speedup vs baseline: 2.0906x; 2.0906x over previous
#include <cuda_runtime.h>
#include <cuda_bf16.h>
#include <math.h>
#include <stdint.h>

#define D 256
#define HH 512
#define MROWS 128
#define NT 512
#define MAX_NODES 65536
#define MAX_LVL 16384

// ---------------- device scratch ----------------
__device__ float g_embeds[MAX_NODES * D];
__device__ int   g_list[6][MAX_LVL];
__device__ int   g_cnt[6];
// bf16 hi/lo transposed weights: [C][K] row-major
__device__ __nv_bfloat16 g_W1bTh[HH * 768],  g_W1bTl[HH * 768];
__device__ __nv_bfloat16 g_W1tTh[HH * 1024], g_W1tTl[HH * 1024];
__device__ __nv_bfloat16 g_W2bTh[D * HH],    g_W2bTl[D * HH];
__device__ __nv_bfloat16 g_W2tTh[D * HH],    g_W2tTl[D * HH];

// ---------------- helpers ----------------
__device__ __forceinline__ uint32_t bfpack(float a, float b) {
    __nv_bfloat162 t = __floats2bfloat162_rn(a, b);
    return *reinterpret_cast<uint32_t*>(&t);
}
__device__ __forceinline__ float bfres(float a) {
    return a - __bfloat162float(__float2bfloat16_rn(a));
}
__device__ __forceinline__ float gelu_exact(float x) {
    return 0.5f * x * (1.0f + erff(x * 0.70710678118654752440f));
}
__device__ __forceinline__ void ldsm4(uint32_t r[4], uint32_t addr) {
    asm volatile("ldmatrix.sync.aligned.m8n8.x4.shared.b16 {%0,%1,%2,%3}, [%4];"
                 : "=r"(r[0]), "=r"(r[1]), "=r"(r[2]), "=r"(r[3]) : "r"(addr));
}
__device__ __forceinline__ void mma16816(float c[4], const uint32_t a[4],
                                         uint32_t b0, uint32_t b1) {
    asm volatile(
        "mma.sync.aligned.m16n8k16.row.col.f32.bf16.bf16.f32 "
        "{%0,%1,%2,%3}, {%4,%5,%6,%7}, {%8,%9}, {%0,%1,%2,%3};"
        : "+f"(c[0]), "+f"(c[1]), "+f"(c[2]), "+f"(c[3])
        : "r"(a[0]), "r"(a[1]), "r"(a[2]), "r"(a[3]), "r"(b0), "r"(b1));
}

// ---------------- smem layout (bytes) ----------------
#define OFF_PTRS   0          // uint64_t [128][4]
#define OFF_NODE   4096
#define OFF_IDX    4608
#define OFF_VALID  5120
#define OFF_MU     5632
#define OFF_RS     6144
#define POOL       8192
#define PA1H (POOL)              // [128][40e] stride 80B
#define PA1L (POOL + 10240)
#define PB1H (POOL + 20480)      // [128][40e]
#define PB1L (POOL + 30720)
#define PA2H (POOL + 40960)      // [128][136e] stride 272B
#define PA2L (POOL + 75776)
#define PB2H (POOL + 110592)     // [256][40e]
#define PB2L (POOL + 131072)
#define PZ   (POOL)              // zbuf f32 [128][260] stride 1040B (aliases tiles)
#define SMEM_TOTAL (POOL + 151552)

// ---------------- small kernels ----------------
__global__ void init_embeds_kernel(const int* __restrict__ comp_ids,
                                   const float* __restrict__ comp_table) {
    int node = blockIdx.x;
    int c = threadIdx.x;
    g_embeds[node * D + c] = comp_table[comp_ids[node] * D + c];
}
__global__ void reset_kernel() { if (threadIdx.x < 6) g_cnt[threadIdx.x] = 0; }

__global__ void compact_kernel(const int* __restrict__ lvl2, int n2,
                               const int* __restrict__ lvl1, int n1,
                               const int* __restrict__ lvl0, int n0,
                               const int* __restrict__ third) {
    int i = blockIdx.x * blockDim.x + threadIdx.x;
    int lvl, j;
    const int* idx;
    if (i < n2)                { lvl = 0; j = i;            idx = lvl2; }
    else if (i < n2 + n1)      { lvl = 1; j = i - n2;       idx = lvl1; }
    else if (i < n2 + n1 + n0) { lvl = 2; j = i - n2 - n1;  idx = lvl0; }
    else return;
    int node = idx[j];
    bool tern = (third[node] >= 0);
    int slot = lvl * 2 + (tern ? 0 : 1);
    int pos = atomicAdd(&g_cnt[slot], 1);
    g_list[slot][pos] = j;
}

// transpose + hi/lo bf16 split: in [K][C] fp32 -> oh/ol [C][K] bf16
__global__ void convsplit_kernel(const float* __restrict__ in,
                                 __nv_bfloat16* __restrict__ oh,
                                 __nv_bfloat16* __restrict__ ol, int K, int C) {
    __shared__ float tile[32][33];
    int c0 = blockIdx.x * 32, k0 = blockIdx.y * 32;
    int tx = threadIdx.x, ty = threadIdx.y;   // 32 x 8
    #pragma unroll
    for (int r = 0; r < 32; r += 8)
        tile[ty + r][tx] = in[(size_t)(k0 + ty + r) * C + c0 + tx];
    __syncthreads();
    #pragma unroll
    for (int r = 0; r < 32; r += 8) {
        float f = tile[tx][ty + r];
        __nv_bfloat16 h = __float2bfloat16_rn(f);
        float fl = f - __bfloat162float(h);
        size_t o = (size_t)(c0 + ty + r) * K + k0 + tx;
        oh[o] = h;
        ol[o] = __float2bfloat16_rn(fl);
    }
}

// ---------------- main HMMA level kernel ----------------
__global__ __launch_bounds__(NT, 1)
void level_mma_kernel(int slot, int tern, int K1,
                      const int* __restrict__ lvl_idx,
                      const int* __restrict__ lc, const int* __restrict__ rc,
                      const int* __restrict__ tcld,
                      const int* __restrict__ opids,
                      const float* __restrict__ op_table,
                      const __nv_bfloat16* __restrict__ W1Th,
                      const __nv_bfloat16* __restrict__ W1Tl,
                      const __nv_bfloat16* __restrict__ W2Th,
                      const __nv_bfloat16* __restrict__ W2Tl,
                      const float* __restrict__ b1, const float* __restrict__ b2,
                      const float* __restrict__ gma, const float* __restrict__ bta,
                      float* __restrict__ final_out) {
    extern __shared__ char smem[];
    int cnt = g_cnt[slot];
    int base = blockIdx.x * MROWS;
    if (base >= cnt) return;

    int t = threadIdx.x;
    int lane = t & 31, wid = t >> 5;
    uint32_t sb = (uint32_t)__cvta_generic_to_shared(smem);

    uint64_t* sm_ptr  = (uint64_t*)(smem + OFF_PTRS);
    int* sm_node  = (int*)(smem + OFF_NODE);
    int* sm_idx   = (int*)(smem + OFF_IDX);
    int* sm_valid = (int*)(smem + OFF_VALID);
    float* sm_mu  = (float*)(smem + OFF_MU);
    float* sm_rs  = (float*)(smem + OFF_RS);

    // row meta
    const int* rows = g_list[slot];
    if (t < MROWS) {
        int rr = min(base + t, cnt - 1);
        int i = rows[rr];
        int node = lvl_idx[i];
        sm_node[t] = node;
        sm_idx[t] = i;
        sm_valid[t] = (base + t < cnt) ? 1 : 0;
        sm_ptr[t * 4 + 0] = (uint64_t)(op_table + (size_t)opids[node] * D);
        sm_ptr[t * 4 + 1] = (uint64_t)(g_embeds + (size_t)lc[node] * D);
        sm_ptr[t * 4 + 2] = (uint64_t)(g_embeds + (size_t)rc[node] * D);
        sm_ptr[t * 4 + 3] = tern ? (uint64_t)(g_embeds + (size_t)tcld[node] * D)
                                 : (uint64_t)(g_embeds + (size_t)lc[node] * D);
    }
    __syncthreads();

    int wm = wid & 3, wn = wid >> 2;
    int m0 = wm * 32;
    int laneA_row  = lane & 15;
    int laneA_koff = (lane >> 4) * 16;                  // bytes
    int laneB_nrow = (lane & 7) + ((lane & 16) >> 1);
    int laneB_koff = ((lane >> 3) & 1) * 16;            // bytes

    float c2[2][8][4];
    #pragma unroll
    for (int i = 0; i < 2; i++)
        #pragma unroll
        for (int j = 0; j < 8; j++)
            #pragma unroll
            for (int r = 0; r < 4; r++) c2[i][j][r] = 0.0f;

    int nkc = K1 >> 5;

    for (int ph = 0; ph < 4; ph++) {
        float c1[2][4][4];
        #pragma unroll
        for (int i = 0; i < 2; i++)
            #pragma unroll
            for (int j = 0; j < 4; j++)
                #pragma unroll
                for (int r = 0; r < 4; r++) c1[i][j][r] = 0.0f;

        // ================= GEMM1: K chunks of 32 =================
        for (int kc = 0; kc < nkc; kc++) {
            // ---- gather A1 chunk [128][32] hi/lo ----
            {
                int row = t >> 2, q = t & 3;
                int k0 = kc * 32, seg = k0 >> 8, soff = (k0 & 255) + q * 8;
                const float4* src = (const float4*)((const float*)sm_ptr[row * 4 + seg] + soff);
                float4 a = src[0], b = src[1];
                uint4 vh, vl;
                vh.x = bfpack(a.x, a.y); vh.y = bfpack(a.z, a.w);
                vh.z = bfpack(b.x, b.y); vh.w = bfpack(b.z, b.w);
                vl.x = bfpack(bfres(a.x), bfres(a.y)); vl.y = bfpack(bfres(a.z), bfres(a.w));
                vl.z = bfpack(bfres(b.x), bfres(b.y)); vl.w = bfpack(bfres(b.z), bfres(b.w));
                *(uint4*)(smem + PA1H + row * 80 + q * 16) = vh;
                *(uint4*)(smem + PA1L + row * 80 + q * 16) = vl;
            }
            // ---- load B1 chunk: W1T rows [ph*128 .. +128), k [kc*32 .. +32) ----
            {
                int plane = t >> 8, r = (t & 255) >> 1, half = t & 1;
                const __nv_bfloat16* Wp = plane ? W1Tl : W1Th;
                const uint4* src = (const uint4*)(Wp + (size_t)(ph * 128 + r) * K1
                                                  + kc * 32 + half * 16);
                uint4 v0 = src[0], v1 = src[1];
                char* dst = smem + (plane ? PB1L : PB1H) + r * 80 + half * 32;
                *(uint4*)(dst) = v0;
                *(uint4*)(dst + 16) = v1;
            }
            __syncthreads();

            int n0 = wn * 32;
            #pragma unroll
            for (int pr = 0; pr < 3; pr++) {
                int Ab = (pr == 2) ? PA1L : PA1H;
                int Bb = (pr == 1) ? PB1L : PB1H;
                #pragma unroll
                for (int ks = 0; ks < 2; ks++) {
                    int kb = ks * 32;
                    uint32_t a0[4], a1[4], bb0[4], bb1[4];
                    ldsm4(a0, sb + Ab + (m0 + laneA_row) * 80 + kb + laneA_koff);
                    ldsm4(a1, sb + Ab + (m0 + 16 + laneA_row) * 80 + kb + laneA_koff);
                    ldsm4(bb0, sb + Bb + (n0 + laneB_nrow) * 80 + kb + laneB_koff);
                    ldsm4(bb1, sb + Bb + (n0 + 16 + laneB_nrow) * 80 + kb + laneB_koff);
                    mma16816(c1[0][0], a0, bb0[0], bb0[1]);
                    mma16816(c1[0][1], a0, bb0[2], bb0[3]);
                    mma16816(c1[0][2], a0, bb1[0], bb1[1]);
                    mma16816(c1[0][3], a0, bb1[2], bb1[3]);
                    mma16816(c1[1][0], a1, bb0[0], bb0[1]);
                    mma16816(c1[1][1], a1, bb0[2], bb0[3]);
                    mma16816(c1[1][2], a1, bb1[0], bb1[1]);
                    mma16816(c1[1][3], a1, bb1[2], bb1[3]);
                }
            }
            __syncthreads();
        }

        // ================= GELU -> A2 tiles (hi/lo) =================
        {
            int n0 = wn * 32;
            #pragma unroll
            for (int j = 0; j < 4; j++) {
                int ncol = n0 + j * 8 + (lane & 3) * 2;
                float2 bb = *(const float2*)(b1 + ph * 128 + ncol);
                #pragma unroll
                for (int i = 0; i < 2; i++) {
                    int mt = m0 + i * 16 + (lane >> 2);
                    float h0 = gelu_exact(c1[i][j][0] + bb.x);
                    float h1 = gelu_exact(c1[i][j][1] + bb.y);
                    *(uint32_t*)(smem + PA2H + mt * 272 + ncol * 2) = bfpack(h0, h1);
                    *(uint32_t*)(smem + PA2L + mt * 272 + ncol * 2) =
                        bfpack(bfres(h0), bfres(h1));
                    float h2 = gelu_exact(c1[i][j][2] + bb.x);
                    float h3 = gelu_exact(c1[i][j][3] + bb.y);
                    *(uint32_t*)(smem + PA2H + (mt + 8) * 272 + ncol * 2) = bfpack(h2, h3);
                    *(uint32_t*)(smem + PA2L + (mt + 8) * 272 + ncol * 2) =
                        bfpack(bfres(h2), bfres(h3));
                }
            }
        }
        __syncthreads();

        // ================= GEMM2: this phase's k window (128), chunks of 32 =================
        for (int kc2 = 0; kc2 < 4; kc2++) {
            // ---- load B2 chunk: W2T rows [0..256), k = ph*128 + kc2*32 ----
            {
                int plane = t >> 8, r = t & 255;
                const __nv_bfloat16* Wp = plane ? W2Tl : W2Th;
                const uint4* src = (const uint4*)(Wp + (size_t)r * HH + ph * 128 + kc2 * 32);
                uint4 v0 = src[0], v1 = src[1], v2 = src[2], v3 = src[3];
                char* dst = smem + (plane ? PB2L : PB2H) + r * 80;
                *(uint4*)(dst)      = v0;
                *(uint4*)(dst + 16) = v1;
                *(uint4*)(dst + 32) = v2;
                *(uint4*)(dst + 48) = v3;
            }
            __syncthreads();

            int n0 = wn * 64;
            #pragma unroll
            for (int pr = 0; pr < 3; pr++) {
                int Ab = (pr == 2) ? PA2L : PA2H;
                int Bb = (pr == 1) ? PB2L : PB2H;
                #pragma unroll
                for (int ks = 0; ks < 2; ks++) {
                    int kbA = kc2 * 64 + ks * 32;
                    int kbB = ks * 32;
                    uint32_t a0[4], a1[4];
                    ldsm4(a0, sb + Ab + (m0 + laneA_row) * 272 + kbA + laneA_koff);
                    ldsm4(a1, sb + Ab + (m0 + 16 + laneA_row) * 272 + kbA + laneA_koff);
                    #pragma unroll
                    for (int jj = 0; jj < 4; jj++) {
                        uint32_t bb[4];
                        ldsm4(bb, sb + Bb + (n0 + jj * 16 + laneB_nrow) * 80 + kbB + laneB_koff);
                        mma16816(c2[0][jj * 2],     a0, bb[0], bb[1]);
                        mma16816(c2[0][jj * 2 + 1], a0, bb[2], bb[3]);
                        mma16816(c2[1][jj * 2],     a1, bb[0], bb[1]);
                        mma16816(c2[1][jj * 2 + 1], a1, bb[2], bb[3]);
                    }
                }
            }
            __syncthreads();
        }
    }

    // ================= epilogue: z = y + b2 + residual -> zbuf =================
    {
        int n0 = wn * 64;
        #pragma unroll
        for (int i = 0; i < 2; i++) {
            #pragma unroll
            for (int rh = 0; rh < 2; rh++) {
                int m = m0 + i * 16 + rh * 8 + (lane >> 2);
                const float* lp = (const float*)sm_ptr[m * 4 + 1];
                const float* rp = (const float*)sm_ptr[m * 4 + 2];
                const float* tp = (const float*)sm_ptr[m * 4 + 3];
                #pragma unroll
                for (int j = 0; j < 8; j++) {
                    int n = n0 + j * 8 + (lane & 3) * 2;
                    float2 bv = *(const float2*)(b2 + n);
                    float y0 = c2[i][j][rh * 2]     + bv.x;
                    float y1 = c2[i][j][rh * 2 + 1] + bv.y;
                    float2 lv = *(const float2*)(lp + n);
                    float2 rv = *(const float2*)(rp + n);
                    if (tern) {
                        float2 tv = *(const float2*)(tp + n);
                        y0 += (lv.x + rv.x + tv.x) * (1.0f / 3.0f);
                        y1 += (lv.y + rv.y + tv.y) * (1.0f / 3.0f);
                    } else {
                        y0 += lv.x + rv.x;
                        y1 += lv.y + rv.y;
                    }
                    *(float2*)(smem + PZ + m * 1040 + n * 4) = make_float2(y0, y1);
                }
            }
        }
    }
    __syncthreads();

    // ================= LayerNorm =================
    if (t < MROWS) {
        const float* zr = (const float*)(smem + PZ + t * 1040);
        float s = 0.0f, s2 = 0.0f;
        #pragma unroll 8
        for (int c = 0; c < D; c++) {
            float v = zr[c];
            s += v;
            s2 += v * v;
        }
        float mu = s * (1.0f / 256.0f);
        float var = s2 * (1.0f / 256.0f) - mu * mu;
        sm_mu[t] = mu;
        sm_rs[t] = rsqrtf(var + 1e-5f);
    }
    __syncthreads();

    for (int idx = t; idx < MROWS * 64; idx += NT) {
        int row = idx >> 6, q = idx & 63;
        if (!sm_valid[row]) continue;
        float mu = sm_mu[row], rs = sm_rs[row];
        const float* zr = (const float*)(smem + PZ + row * 1040) + q * 4;
        float4 g4 = *(const float4*)(gma + q * 4);
        float4 be = *(const float4*)(bta + q * 4);
        float4 o;
        o.x = (zr[0] - mu) * rs * g4.x + be.x;
        o.y = (zr[1] - mu) * rs * g4.y + be.y;
        o.z = (zr[2] - mu) * rs * g4.z + be.z;
        o.w = (zr[3] - mu) * rs * g4.w + be.w;
        float* outp = final_out ? (final_out + (size_t)sm_idx[row] * D)
                                : (g_embeds + (size_t)sm_node[row] * D);
        *(float4*)(outp + q * 4) = o;
    }
}

// ---------------- launcher ----------------
extern "C" void kernel_launch(void* const* d_in, const int* in_sizes, int n_in,
                              void* d_out, int out_size) {
    const int*   comp_ids   = (const int*)d_in[0];
    const int*   op_ids     = (const int*)d_in[1];
    const int*   lc         = (const int*)d_in[2];
    const int*   rc         = (const int*)d_in[3];
    const int*   tc         = (const int*)d_in[4];
    const int*   l2         = (const int*)d_in[5];
    const int*   l1         = (const int*)d_in[6];
    const int*   l0         = (const int*)d_in[7];
    const float* comp_table = (const float*)d_in[8];
    const float* op_table   = (const float*)d_in[9];
    const float* W1b        = (const float*)d_in[10];
    const float* b1b        = (const float*)d_in[11];
    const float* W2b        = (const float*)d_in[12];
    const float* b2b        = (const float*)d_in[13];
    const float* W1t        = (const float*)d_in[14];
    const float* b1t        = (const float*)d_in[15];
    const float* W2t        = (const float*)d_in[16];
    const float* b2t        = (const float*)d_in[17];
    const float* gma        = (const float*)d_in[18];
    const float* bta        = (const float*)d_in[19];

    int n_nodes = in_sizes[0];
    int n2 = in_sizes[5], n1 = in_sizes[6], n0 = in_sizes[7];

    cudaFuncSetAttribute(level_mma_kernel, cudaFuncAttributeMaxDynamicSharedMemorySize,
                         SMEM_TOTAL);

    __nv_bfloat16 *w1bh, *w1bl, *w1th, *w1tl, *w2bh, *w2bl, *w2th, *w2tl;
    cudaGetSymbolAddress((void**)&w1bh, g_W1bTh);
    cudaGetSymbolAddress((void**)&w1bl, g_W1bTl);
    cudaGetSymbolAddress((void**)&w1th, g_W1tTh);
    cudaGetSymbolAddress((void**)&w1tl, g_W1tTl);
    cudaGetSymbolAddress((void**)&w2bh, g_W2bTh);
    cudaGetSymbolAddress((void**)&w2bl, g_W2bTl);
    cudaGetSymbolAddress((void**)&w2th, g_W2tTh);
    cudaGetSymbolAddress((void**)&w2tl, g_W2tTl);

    dim3 tb(32, 8);
    convsplit_kernel<<<dim3(HH / 32, 768 / 32),  tb>>>(W1b, w1bh, w1bl, 768,  HH);
    convsplit_kernel<<<dim3(HH / 32, 1024 / 32), tb>>>(W1t, w1th, w1tl, 1024, HH);
    convsplit_kernel<<<dim3(D / 32,  HH / 32),   tb>>>(W2b, w2bh, w2bl, HH,   D);
    convsplit_kernel<<<dim3(D / 32,  HH / 32),   tb>>>(W2t, w2th, w2tl, HH,   D);

    init_embeds_kernel<<<n_nodes, D>>>(comp_ids, comp_table);
    reset_kernel<<<1, 32>>>();
    int tot = n2 + n1 + n0;
    compact_kernel<<<(tot + 255) / 256, 256>>>(l2, n2, l1, n1, l0, n0, tc);

    int ns[3] = {n2, n1, n0};
    const int* lidx[3] = {l2, l1, l0};
    for (int lvl = 0; lvl < 3; lvl++) {
        int nb = (ns[lvl] + MROWS - 1) / MROWS;
        float* fout = (lvl == 2) ? (float*)d_out : nullptr;
        // ternary slot
        level_mma_kernel<<<nb, NT, SMEM_TOTAL>>>(
            lvl * 2, 1, 1024, lidx[lvl], lc, rc, tc, op_ids, op_table,
            w1th, w1tl, w2th, w2tl, b1t, b2t, gma, bta, fout);
        // binary slot
        level_mma_kernel<<<nb, NT, SMEM_TOTAL>>>(
            lvl * 2 + 1, 0, 768, lidx[lvl], lc, rc, tc, op_ids, op_table,
            w1bh, w1bl, w2bh, w2bl, b1b, b2b, gma, bta, fout);
    }
}

// round 5
// speedup vs baseline: 3.0834x; 1.4749x over previous
#include <cuda_runtime.h>
#include <cuda_bf16.h>
#include <math.h>
#include <stdint.h>

#define D 256
#define HH 512
#define MROWS 64
#define NT 256
#define MAX_NODES 65536
#define MAX_LVL 16384

// ---------------- device scratch ----------------
__device__ float g_embeds[MAX_NODES * D];
__device__ __nv_bfloat16 g_embh[MAX_NODES * D];
__device__ __nv_bfloat16 g_embl[MAX_NODES * D];
__device__ __nv_bfloat16 g_oph[16 * D], g_opl[16 * D];
__device__ int   g_list[6][MAX_LVL];
__device__ int   g_cnt[6];
__device__ __nv_bfloat16 g_W1bTh[HH * 768],  g_W1bTl[HH * 768];
__device__ __nv_bfloat16 g_W1tTh[HH * 1024], g_W1tTl[HH * 1024];
__device__ __nv_bfloat16 g_W2bTh[D * HH],    g_W2bTl[D * HH];
__device__ __nv_bfloat16 g_W2tTh[D * HH],    g_W2tTl[D * HH];

// ---------------- helpers ----------------
__device__ __forceinline__ uint32_t bfpack(float a, float b) {
    __nv_bfloat162 t = __floats2bfloat162_rn(a, b);
    return *reinterpret_cast<uint32_t*>(&t);
}
__device__ __forceinline__ float bfres(float a) {
    return a - __bfloat162float(__float2bfloat16_rn(a));
}
__device__ __forceinline__ float gelu_exact(float x) {
    return 0.5f * x * (1.0f + erff(x * 0.70710678118654752440f));
}
__device__ __forceinline__ void ldsm4(uint32_t r[4], uint32_t addr) {
    asm volatile("ldmatrix.sync.aligned.m8n8.x4.shared.b16 {%0,%1,%2,%3}, [%4];"
                 : "=r"(r[0]), "=r"(r[1]), "=r"(r[2]), "=r"(r[3]) : "r"(addr));
}
__device__ __forceinline__ void mma16816(float c[4], const uint32_t a[4],
                                         uint32_t b0, uint32_t b1) {
    asm volatile(
        "mma.sync.aligned.m16n8k16.row.col.f32.bf16.bf16.f32 "
        "{%0,%1,%2,%3}, {%4,%5,%6,%7}, {%8,%9}, {%0,%1,%2,%3};"
        : "+f"(c[0]), "+f"(c[1]), "+f"(c[2]), "+f"(c[3])
        : "r"(a[0]), "r"(a[1]), "r"(a[2]), "r"(a[3]), "r"(b0), "r"(b1));
}

// ---------------- smem layout (bytes) ----------------
#define OFF_PTRH   0
#define OFF_PTRL   2048
#define OFF_PTRF   4096
#define OFF_NODE   6144
#define OFF_IDX    6400
#define OFF_VALID  6656
#define OFF_MU     6912
#define OFF_RS     7168
#define POOL       8192
#define PA1H (POOL)
#define PA1L (POOL + 9216)
#define PB1H (POOL + 18432)
#define PB1L (POOL + 36864)
#define PB2H (POOL)
#define PB2L (POOL + 20480)
#define PA2H (POOL + 55296)
#define PA2L (POOL + 72704)
#define PZ   (POOL)
#define SMEM_TOTAL (POOL + 90112)

// ---------------- small kernels ----------------
__global__ void init_embeds_kernel(const int* __restrict__ comp_ids,
                                   const float* __restrict__ comp_table) {
    int node = blockIdx.x;
    int c = threadIdx.x;
    float f = comp_table[comp_ids[node] * D + c];
    __nv_bfloat16 h = __float2bfloat16_rn(f);
    g_embeds[node * D + c] = f;
    g_embh[node * D + c] = h;
    g_embl[node * D + c] = __float2bfloat16_rn(f - __bfloat162float(h));
}
__global__ void opconv_kernel(const float* __restrict__ op_table, int n) {
    int i = blockIdx.x * blockDim.x + threadIdx.x;
    if (i >= n) return;
    float f = op_table[i];
    __nv_bfloat16 h = __float2bfloat16_rn(f);
    g_oph[i] = h;
    g_opl[i] = __float2bfloat16_rn(f - __bfloat162float(h));
}
__global__ void reset_kernel() { if (threadIdx.x < 6) g_cnt[threadIdx.x] = 0; }

__global__ void compact_kernel(const int* __restrict__ lvl2, int n2,
                               const int* __restrict__ lvl1, int n1,
                               const int* __restrict__ lvl0, int n0,
                               const int* __restrict__ third) {
    int i = blockIdx.x * blockDim.x + threadIdx.x;
    int lvl, j;
    const int* idx;
    if (i < n2)                { lvl = 0; j = i;            idx = lvl2; }
    else if (i < n2 + n1)      { lvl = 1; j = i - n2;       idx = lvl1; }
    else if (i < n2 + n1 + n0) { lvl = 2; j = i - n2 - n1;  idx = lvl0; }
    else return;
    int node = idx[j];
    bool tern = (third[node] >= 0);
    int slot = lvl * 2 + (tern ? 0 : 1);
    int pos = atomicAdd(&g_cnt[slot], 1);
    g_list[slot][pos] = j;
}

__global__ void convsplit_kernel(const float* __restrict__ in,
                                 __nv_bfloat16* __restrict__ oh,
                                 __nv_bfloat16* __restrict__ ol, int K, int C) {
    __shared__ float tile[32][33];
    int c0 = blockIdx.x * 32, k0 = blockIdx.y * 32;
    int tx = threadIdx.x, ty = threadIdx.y;
    #pragma unroll
    for (int r = 0; r < 32; r += 8)
        tile[ty + r][tx] = in[(size_t)(k0 + ty + r) * C + c0 + tx];
    __syncthreads();
    #pragma unroll
    for (int r = 0; r < 32; r += 8) {
        float f = tile[tx][ty + r];
        __nv_bfloat16 h = __float2bfloat16_rn(f);
        float fl = f - __bfloat162float(h);
        size_t o = (size_t)(c0 + ty + r) * K + k0 + tx;
        oh[o] = h;
        ol[o] = __float2bfloat16_rn(fl);
    }
}

// ---------------- main HMMA level kernel ----------------
__global__ __launch_bounds__(NT, 1)
void level_mma_kernel(int lvl,
                      const int* __restrict__ lvl_idx,
                      const int* __restrict__ lc, const int* __restrict__ rc,
                      const int* __restrict__ tcld,
                      const int* __restrict__ opids,
                      const __nv_bfloat16* __restrict__ W1bTh, const __nv_bfloat16* __restrict__ W1bTl,
                      const __nv_bfloat16* __restrict__ W2bTh, const __nv_bfloat16* __restrict__ W2bTl,
                      const __nv_bfloat16* __restrict__ W1tTh, const __nv_bfloat16* __restrict__ W1tTl,
                      const __nv_bfloat16* __restrict__ W2tTh, const __nv_bfloat16* __restrict__ W2tTl,
                      const float* __restrict__ b1b, const float* __restrict__ b2b,
                      const float* __restrict__ b1t, const float* __restrict__ b2t,
                      const float* __restrict__ gma, const float* __restrict__ bta,
                      float* __restrict__ final_out) {
    extern __shared__ char smem[];
    int nbt = gridDim.x >> 1;
    int tern = (blockIdx.x < (unsigned)nbt) ? 1 : 0;
    int slot = lvl * 2 + (tern ? 0 : 1);
    int cnt = g_cnt[slot];
    int blk = tern ? blockIdx.x : (blockIdx.x - nbt);
    int base = blk * MROWS;
    if (base >= cnt) return;

    const int K1 = tern ? 1024 : 768;
    const __nv_bfloat16* W1Th = tern ? W1tTh : W1bTh;
    const __nv_bfloat16* W1Tl = tern ? W1tTl : W1bTl;
    const __nv_bfloat16* W2Th = tern ? W2tTh : W2bTh;
    const __nv_bfloat16* W2Tl = tern ? W2tTl : W2bTl;
    const float* b1 = tern ? b1t : b1b;
    const float* b2 = tern ? b2t : b2b;

    int t = threadIdx.x;
    int lane = t & 31, wid = t >> 5;
    uint32_t sb = (uint32_t)__cvta_generic_to_shared(smem);

    uint64_t* sm_ptrh = (uint64_t*)(smem + OFF_PTRH);
    uint64_t* sm_ptrl = (uint64_t*)(smem + OFF_PTRL);
    uint64_t* sm_ptrf = (uint64_t*)(smem + OFF_PTRF);
    int* sm_node  = (int*)(smem + OFF_NODE);
    int* sm_idx   = (int*)(smem + OFF_IDX);
    int* sm_valid = (int*)(smem + OFF_VALID);
    float* sm_mu  = (float*)(smem + OFF_MU);
    float* sm_rs  = (float*)(smem + OFF_RS);

    const int* rows = g_list[slot];
    if (t < MROWS) {
        int rr = min(base + t, cnt - 1);
        int i = rows[rr];
        int node = lvl_idx[i];
        sm_node[t] = node;
        sm_idx[t] = i;
        sm_valid[t] = (base + t < cnt) ? 1 : 0;
        size_t oo = (size_t)opids[node] * D;
        size_t lo_ = (size_t)lc[node] * D;
        size_t ro_ = (size_t)rc[node] * D;
        size_t to_ = tern ? (size_t)tcld[node] * D : lo_;
        sm_ptrh[t * 4 + 0] = (uint64_t)(g_oph + oo);
        sm_ptrh[t * 4 + 1] = (uint64_t)(g_embh + lo_);
        sm_ptrh[t * 4 + 2] = (uint64_t)(g_embh + ro_);
        sm_ptrh[t * 4 + 3] = (uint64_t)(g_embh + to_);
        sm_ptrl[t * 4 + 0] = (uint64_t)(g_opl + oo);
        sm_ptrl[t * 4 + 1] = (uint64_t)(g_embl + lo_);
        sm_ptrl[t * 4 + 2] = (uint64_t)(g_embl + ro_);
        sm_ptrl[t * 4 + 3] = (uint64_t)(g_embl + to_);
        sm_ptrf[t * 4 + 1] = (uint64_t)(g_embeds + lo_);
        sm_ptrf[t * 4 + 2] = (uint64_t)(g_embeds + ro_);
        sm_ptrf[t * 4 + 3] = (uint64_t)(g_embeds + to_);
    }
    __syncthreads();

    int wm = wid & 1, wn = wid >> 1;
    int m0 = wm * 32;
    int laneA_row  = lane & 15;
    int laneA_koff = (lane >> 4) * 16;
    int laneB_nrow = (lane & 7) + ((lane & 16) >> 1);
    int laneB_koff = ((lane >> 3) & 1) * 16;

    float c2[2][8][4];
    #pragma unroll
    for (int i = 0; i < 2; i++)
        #pragma unroll
        for (int j = 0; j < 8; j++)
            #pragma unroll
            for (int r = 0; r < 4; r++) c2[i][j][r] = 0.0f;

    int nkc = K1 >> 6;

    for (int ph = 0; ph < 4; ph++) {
        float c1[2][4][4];
        #pragma unroll
        for (int i = 0; i < 2; i++)
            #pragma unroll
            for (int j = 0; j < 4; j++)
                #pragma unroll
                for (int r = 0; r < 4; r++) c1[i][j][r] = 0.0f;

        for (int kc = 0; kc < nkc; kc++) {
            {
                int row = t >> 2, q = t & 3;
                int k0 = kc * 64, seg = k0 >> 8, soff = k0 & 255;
                const uint4* sh = (const uint4*)((const __nv_bfloat16*)sm_ptrh[row * 4 + seg] + soff);
                const uint4* sl = (const uint4*)((const __nv_bfloat16*)sm_ptrl[row * 4 + seg] + soff);
                uint4 h0 = sh[q * 2], h1 = sh[q * 2 + 1];
                uint4 l0 = sl[q * 2], l1 = sl[q * 2 + 1];
                char* dh = smem + PA1H + row * 144 + q * 32;
                char* dl = smem + PA1L + row * 144 + q * 32;
                *(uint4*)(dh)      = h0;
                *(uint4*)(dh + 16) = h1;
                *(uint4*)(dl)      = l0;
                *(uint4*)(dl + 16) = l1;
            }
            {
                int r = t >> 1, half = t & 1;
                const uint4* sh = (const uint4*)(W1Th + (size_t)(ph * 128 + r) * K1 + kc * 64 + half * 32);
                const uint4* sl = (const uint4*)(W1Tl + (size_t)(ph * 128 + r) * K1 + kc * 64 + half * 32);
                char* dh = smem + PB1H + r * 144 + half * 64;
                char* dl = smem + PB1L + r * 144 + half * 64;
                #pragma unroll
                for (int j = 0; j < 4; j++) *(uint4*)(dh + j * 16) = sh[j];
                #pragma unroll
                for (int j = 0; j < 4; j++) *(uint4*)(dl + j * 16) = sl[j];
            }
            __syncthreads();

            int n0 = wn * 32;
            #pragma unroll
            for (int pr = 0; pr < 3; pr++) {
                int Ab = (pr == 2) ? PA1L : PA1H;
                int Bb = (pr == 1) ? PB1L : PB1H;
                #pragma unroll
                for (int ks = 0; ks < 4; ks++) {
                    int kb = ks * 32;
                    uint32_t a0[4], a1[4], bb0[4], bb1[4];
                    ldsm4(a0, sb + Ab + (m0 + laneA_row) * 144 + kb + laneA_koff);
                    ldsm4(a1, sb + Ab + (m0 + 16 + laneA_row) * 144 + kb + laneA_koff);
                    ldsm4(bb0, sb + Bb + (n0 + laneB_nrow) * 144 + kb + laneB_koff);
                    ldsm4(bb1, sb + Bb + (n0 + 16 + laneB_nrow) * 144 + kb + laneB_koff);
                    mma16816(c1[0][0], a0, bb0[0], bb0[1]);
                    mma16816(c1[0][1], a0, bb0[2], bb0[3]);
                    mma16816(c1[0][2], a0, bb1[0], bb1[1]);
                    mma16816(c1[0][3], a0, bb1[2], bb1[3]);
                    mma16816(c1[1][0], a1, bb0[0], bb0[1]);
                    mma16816(c1[1][1], a1, bb0[2], bb0[3]);
                    mma16816(c1[1][2], a1, bb1[0], bb1[1]);
                    mma16816(c1[1][3], a1, bb1[2], bb1[3]);
                }
            }
            __syncthreads();
        }

        {
            int n0 = wn * 32;
            #pragma unroll
            for (int j = 0; j < 4; j++) {
                int ncol = n0 + j * 8 + (lane & 3) * 2;
                float2 bb = *(const float2*)(b1 + ph * 128 + ncol);
                #pragma unroll
                for (int i = 0; i < 2; i++) {
                    int mt = m0 + i * 16 + (lane >> 2);
                    float h0 = gelu_exact(c1[i][j][0] + bb.x);
                    float h1 = gelu_exact(c1[i][j][1] + bb.y);
                    *(uint32_t*)(smem + PA2H + mt * 272 + ncol * 2) = bfpack(h0, h1);
                    *(uint32_t*)(smem + PA2L + mt * 272 + ncol * 2) = bfpack(bfres(h0), bfres(h1));
                    float h2 = gelu_exact(c1[i][j][2] + bb.x);
                    float h3 = gelu_exact(c1[i][j][3] + bb.y);
                    *(uint32_t*)(smem + PA2H + (mt + 8) * 272 + ncol * 2) = bfpack(h2, h3);
                    *(uint32_t*)(smem + PA2L + (mt + 8) * 272 + ncol * 2) = bfpack(bfres(h2), bfres(h3));
                }
            }
        }
        __syncthreads();

        for (int kc2 = 0; kc2 < 4; kc2++) {
            {
                int r = t;
                const uint4* sh = (const uint4*)(W2Th + (size_t)r * HH + ph * 128 + kc2 * 32);
                const uint4* sl = (const uint4*)(W2Tl + (size_t)r * HH + ph * 128 + kc2 * 32);
                char* dh = smem + PB2H + r * 80;
                char* dl = smem + PB2L + r * 80;
                #pragma unroll
                for (int j = 0; j < 4; j++) *(uint4*)(dh + j * 16) = sh[j];
                #pragma unroll
                for (int j = 0; j < 4; j++) *(uint4*)(dl + j * 16) = sl[j];
            }
            __syncthreads();

            int n0 = wn * 64;
            #pragma unroll
            for (int pr = 0; pr < 3; pr++) {
                int Ab = (pr == 2) ? PA2L : PA2H;
                int Bb = (pr == 1) ? PB2L : PB2H;
                #pragma unroll
                for (int ks = 0; ks < 2; ks++) {
                    int kbA = kc2 * 64 + ks * 32;
                    int kbB = ks * 32;
                    uint32_t a0[4], a1[4];
                    ldsm4(a0, sb + Ab + (m0 + laneA_row) * 272 + kbA + laneA_koff);
                    ldsm4(a1, sb + Ab + (m0 + 16 + laneA_row) * 272 + kbA + laneA_koff);
                    #pragma unroll
                    for (int jj = 0; jj < 4; jj++) {
                        uint32_t bb[4];
                        ldsm4(bb, sb + Bb + (n0 + jj * 16 + laneB_nrow) * 80 + kbB + laneB_koff);
                        mma16816(c2[0][jj * 2],     a0, bb[0], bb[1]);
                        mma16816(c2[0][jj * 2 + 1], a0, bb[2], bb[3]);
                        mma16816(c2[1][jj * 2],     a1, bb[0], bb[1]);
                        mma16816(c2[1][jj * 2 + 1], a1, bb[2], bb[3]);
                    }
                }
            }
            __syncthreads();
        }
    }

    {
        int n0 = wn * 64;
        #pragma unroll
        for (int i = 0; i < 2; i++) {
            #pragma unroll
            for (int rh = 0; rh < 2; rh++) {
                int m = m0 + i * 16 + rh * 8 + (lane >> 2);
                const float* lp = (const float*)sm_ptrf[m * 4 + 1];
                const float* rp = (const float*)sm_ptrf[m * 4 + 2];
                const float* tp = (const float*)sm_ptrf[m * 4 + 3];
                #pragma unroll
                for (int j = 0; j < 8; j++) {
                    int n = n0 + j * 8 + (lane & 3) * 2;
                    float2 bv = *(const float2*)(b2 + n);
                    float y0 = c2[i][j][rh * 2]     + bv.x;
                    float y1 = c2[i][j][rh * 2 + 1] + bv.y;
                    float2 lv = *(const float2*)(lp + n);
                    float2 rv = *(const float2*)(rp + n);
                    if (tern) {
                        float2 tv = *(const float2*)(tp + n);
                        y0 += (lv.x + rv.x + tv.x) * (1.0f / 3.0f);
                        y1 += (lv.y + rv.y + tv.y) * (1.0f / 3.0f);
                    } else {
                        y0 += lv.x + rv.x;
                        y1 += lv.y + rv.y;
                    }
                    *(float2*)(smem + PZ + m * 1040 + n * 4) = make_float2(y0, y1);
                }
            }
        }
    }
    __syncthreads();

    if (t < MROWS) {
        const float* zr = (const float*)(smem + PZ + t * 1040);
        float s = 0.0f, s2 = 0.0f;
        #pragma unroll 8
        for (int c = 0; c < D; c++) {
            float v = zr[c];
            s += v;
            s2 += v * v;
        }
        float mu = s * (1.0f / 256.0f);
        float var = s2 * (1.0f / 256.0f) - mu * mu;
        sm_mu[t] = mu;
        sm_rs[t] = rsqrtf(var + 1e-5f);
    }
    __syncthreads();

    for (int idx = t; idx < MROWS * 64; idx += NT) {
        int row = idx >> 6, q = idx & 63;
        if (!sm_valid[row]) continue;
        float mu = sm_mu[row], rs = sm_rs[row];
        const float* zr = (const float*)(smem + PZ + row * 1040) + q * 4;
        float4 g4 = *(const float4*)(gma + q * 4);
        float4 be = *(const float4*)(bta + q * 4);
        float4 o;
        o.x = (zr[0] - mu) * rs * g4.x + be.x;
        o.y = (zr[1] - mu) * rs * g4.y + be.y;
        o.z = (zr[2] - mu) * rs * g4.z + be.z;
        o.w = (zr[3] - mu) * rs * g4.w + be.w;
        if (final_out) {
            *(float4*)(final_out + (size_t)sm_idx[row] * D + q * 4) = o;
        } else {
            size_t off = (size_t)sm_node[row] * D + q * 4;
            *(float4*)(g_embeds + off) = o;
            uint2 hv, lv;
            hv.x = bfpack(o.x, o.y);
            hv.y = bfpack(o.z, o.w);
            lv.x = bfpack(bfres(o.x), bfres(o.y));
            lv.y = bfpack(bfres(o.z), bfres(o.w));
            *(uint2*)(g_embh + off) = hv;
            *(uint2*)(g_embl + off) = lv;
        }
    }
}

// ---------------- launcher ----------------
extern "C" void kernel_launch(void* const* d_in, const int* in_sizes, int n_in,
                              void* d_out, int out_size) {
    const int*   comp_ids   = (const int*)d_in[0];
    const int*   op_ids     = (const int*)d_in[1];
    const int*   lc         = (const int*)d_in[2];
    const int*   rc         = (const int*)d_in[3];
    const int*   tc         = (const int*)d_in[4];
    const int*   l2         = (const int*)d_in[5];
    const int*   l1         = (const int*)d_in[6];
    const int*   l0         = (const int*)d_in[7];
    const float* comp_table = (const float*)d_in[8];
    const float* op_table   = (const float*)d_in[9];
    const float* W1b        = (const float*)d_in[10];
    const float* b1b        = (const float*)d_in[11];
    const float* W2b        = (const float*)d_in[12];
    const float* b2b        = (const float*)d_in[13];
    const float* W1t        = (const float*)d_in[14];
    const float* b1t        = (const float*)d_in[15];
    const float* W2t        = (const float*)d_in[16];
    const float* b2t        = (const float*)d_in[17];
    const float* gma        = (const float*)d_in[18];
    const float* bta        = (const float*)d_in[19];

    int n_nodes = in_sizes[0];
    int n_op = in_sizes[9];
    int n2 = in_sizes[5], n1 = in_sizes[6], n0 = in_sizes[7];

    cudaFuncSetAttribute(level_mma_kernel, cudaFuncAttributeMaxDynamicSharedMemorySize,
                         SMEM_TOTAL);

    __nv_bfloat16 *w1bh, *w1bl, *w1th, *w1tl, *w2bh, *w2bl, *w2th, *w2tl;
    cudaGetSymbolAddress((void**)&w1bh, g_W1bTh);
    cudaGetSymbolAddress((void**)&w1bl, g_W1bTl);
    cudaGetSymbolAddress((void**)&w1th, g_W1tTh);
    cudaGetSymbolAddress((void**)&w1tl, g_W1tTl);
    cudaGetSymbolAddress((void**)&w2bh, g_W2bTh);
    cudaGetSymbolAddress((void**)&w2bl, g_W2bTl);
    cudaGetSymbolAddress((void**)&w2th, g_W2tTh);
    cudaGetSymbolAddress((void**)&w2tl, g_W2tTl);

    dim3 tb(32, 8);
    convsplit_kernel<<<dim3(HH / 32, 768 / 32),  tb>>>(W1b, w1bh, w1bl, 768,  HH);
    convsplit_kernel<<<dim3(HH / 32, 1024 / 32), tb>>>(W1t, w1th, w1tl, 1024, HH);
    convsplit_kernel<<<dim3(D / 32,  HH / 32),   tb>>>(W2b, w2bh, w2bl, HH,   D);
    convsplit_kernel<<<dim3(D / 32,  HH / 32),   tb>>>(W2t, w2th, w2tl, HH,   D);

    init_embeds_kernel<<<n_nodes, D>>>(comp_ids, comp_table);
    opconv_kernel<<<(n_op + 255) / 256, 256>>>(op_table, n_op);
    reset_kernel<<<1, 32>>>();
    int tot = n2 + n1 + n0;
    compact_kernel<<<(tot + 255) / 256, 256>>>(l2, n2, l1, n1, l0, n0, tc);

    int ns[3] = {n2, n1, n0};
    const int* lidx[3] = {l2, l1, l0};
    for (int lvl = 0; lvl < 3; lvl++) {
        int nb = (ns[lvl] + MROWS - 1) / MROWS;
        float* fout = (lvl == 2) ? (float*)d_out : nullptr;
        level_mma_kernel<<<2 * nb, NT, SMEM_TOTAL>>>(
            lvl, lidx[lvl], lc, rc, tc, op_ids,
            w1bh, w1bl, w2bh, w2bl, w1th, w1tl, w2th, w2tl,
            b1b, b2b, b1t, b2t, gma, bta, fout);
    }
}

// round 6
// speedup vs baseline: 3.5301x; 1.1449x over previous
#include <cuda_runtime.h>
#include <cuda_bf16.h>
#include <math.h>
#include <stdint.h>

#define D 256
#define HH 512
#define MROWS 64
#define NT 256
#define MAX_NODES 65536
#define MAX_LVL 16384

// ---------------- device scratch ----------------
__device__ float g_embeds[MAX_NODES * D];
__device__ __nv_bfloat16 g_embh[MAX_NODES * D];
__device__ __nv_bfloat16 g_embl[MAX_NODES * D];
__device__ __nv_bfloat16 g_oph[16 * D], g_opl[16 * D];
__device__ int   g_list[6][MAX_LVL];
__device__ int   g_cnt[6];
__device__ __nv_bfloat16 g_W1bTh[HH * 768],  g_W1bTl[HH * 768];
__device__ __nv_bfloat16 g_W1tTh[HH * 1024], g_W1tTl[HH * 1024];
__device__ __nv_bfloat16 g_W2bTh[D * HH],    g_W2bTl[D * HH];
__device__ __nv_bfloat16 g_W2tTh[D * HH],    g_W2tTl[D * HH];

// ---------------- helpers ----------------
__device__ __forceinline__ uint32_t bfpack(float a, float b) {
    __nv_bfloat162 t = __floats2bfloat162_rn(a, b);
    return *reinterpret_cast<uint32_t*>(&t);
}
__device__ __forceinline__ float bfres(float a) {
    return a - __bfloat162float(__float2bfloat16_rn(a));
}
__device__ __forceinline__ float gelu_exact(float x) {
    return 0.5f * x * (1.0f + erff(x * 0.70710678118654752440f));
}
__device__ __forceinline__ void ldsm4(uint32_t r[4], uint32_t addr) {
    asm volatile("ldmatrix.sync.aligned.m8n8.x4.shared.b16 {%0,%1,%2,%3}, [%4];"
                 : "=r"(r[0]), "=r"(r[1]), "=r"(r[2]), "=r"(r[3]) : "r"(addr));
}
__device__ __forceinline__ void mma16816(float c[4], const uint32_t a[4],
                                         uint32_t b0, uint32_t b1) {
    asm volatile(
        "mma.sync.aligned.m16n8k16.row.col.f32.bf16.bf16.f32 "
        "{%0,%1,%2,%3}, {%4,%5,%6,%7}, {%8,%9}, {%0,%1,%2,%3};"
        : "+f"(c[0]), "+f"(c[1]), "+f"(c[2]), "+f"(c[3])
        : "r"(a[0]), "r"(a[1]), "r"(a[2]), "r"(a[3]), "r"(b0), "r"(b1));
}
__device__ __forceinline__ void cpasync16(uint32_t dst, const void* src) {
    asm volatile("cp.async.cg.shared.global [%0], [%1], 16;" :: "r"(dst), "l"(src));
}
#define CP_COMMIT() asm volatile("cp.async.commit_group;" ::: "memory")
#define CP_WAIT0()  asm volatile("cp.async.wait_group 0;" ::: "memory")

// ---------------- smem layout (bytes) ----------------
#define OFF_PTRH   0
#define OFF_PTRL   2048
#define OFF_PTRF   4096
#define OFF_NODE   6144
#define OFF_IDX    6400
#define OFF_VALID  6656
#define OFF_MU     6912
#define OFF_RS     7168
#define POOL       8192
#define G1BUF      55296
#define PA1H_(b) (POOL + (b) * G1BUF)
#define PA1L_(b) (POOL + (b) * G1BUF + 9216)
#define PB1H_(b) (POOL + (b) * G1BUF + 18432)
#define PB1L_(b) (POOL + (b) * G1BUF + 36864)
#define PB2H_(b) (POOL + (b) * 40960)
#define PB2L_(b) (POOL + (b) * 40960 + 20480)
#define PA2H (POOL + 110592)
#define PA2L (POOL + 110592 + 17408)
#define PZ   POOL
#define SMEM_TOTAL (POOL + 110592 + 34816)

// ---------------- merged pre-kernels ----------------
__global__ void convall_kernel(const float* __restrict__ W1b, const float* __restrict__ W1t,
                               const float* __restrict__ W2b, const float* __restrict__ W2t) {
    __shared__ float tile[32][33];
    int bx = blockIdx.x;
    if (bx == 0 && threadIdx.y == 0 && threadIdx.x < 6) g_cnt[threadIdx.x] = 0;
    const float* in;
    __nv_bfloat16 *oh, *ol;
    int K, C, local;
    if (bx < 384)        { in = W1b; oh = g_W1bTh; ol = g_W1bTl; K = 768;  C = 512; local = bx; }
    else if (bx < 896)   { in = W1t; oh = g_W1tTh; ol = g_W1tTl; K = 1024; C = 512; local = bx - 384; }
    else if (bx < 1024)  { in = W2b; oh = g_W2bTh; ol = g_W2bTl; K = 512;  C = 256; local = bx - 896; }
    else                 { in = W2t; oh = g_W2tTh; ol = g_W2tTl; K = 512;  C = 256; local = bx - 1024; }
    int ktiles = K >> 5;
    int kt = local % ktiles, ct = local / ktiles;
    int k0 = kt * 32, c0 = ct * 32;
    int tx = threadIdx.x, ty = threadIdx.y;
    #pragma unroll
    for (int r = 0; r < 32; r += 8)
        tile[ty + r][tx] = in[(size_t)(k0 + ty + r) * C + c0 + tx];
    __syncthreads();
    #pragma unroll
    for (int r = 0; r < 32; r += 8) {
        float f = tile[tx][ty + r];
        __nv_bfloat16 h = __float2bfloat16_rn(f);
        float fl = f - __bfloat162float(h);
        size_t o = (size_t)(c0 + ty + r) * K + k0 + tx;
        oh[o] = h;
        ol[o] = __float2bfloat16_rn(fl);
    }
}

__global__ void init_all_kernel(const int* __restrict__ comp_ids,
                                const float* __restrict__ comp_table,
                                const float* __restrict__ op_table, int n_nodes) {
    int b = blockIdx.x, c = threadIdx.x;
    if (b < n_nodes) {
        float f = comp_table[comp_ids[b] * D + c];
        __nv_bfloat16 h = __float2bfloat16_rn(f);
        g_embeds[b * D + c] = f;
        g_embh[b * D + c] = h;
        g_embl[b * D + c] = __float2bfloat16_rn(f - __bfloat162float(h));
    } else {
        int row = b - n_nodes;
        float f = op_table[row * D + c];
        __nv_bfloat16 h = __float2bfloat16_rn(f);
        g_oph[row * D + c] = h;
        g_opl[row * D + c] = __float2bfloat16_rn(f - __bfloat162float(h));
    }
}

__global__ void compact_kernel(const int* __restrict__ lvl2, int n2,
                               const int* __restrict__ lvl1, int n1,
                               const int* __restrict__ lvl0, int n0,
                               const int* __restrict__ third) {
    int i = blockIdx.x * blockDim.x + threadIdx.x;
    int lvl, j;
    const int* idx;
    if (i < n2)                { lvl = 0; j = i;            idx = lvl2; }
    else if (i < n2 + n1)      { lvl = 1; j = i - n2;       idx = lvl1; }
    else if (i < n2 + n1 + n0) { lvl = 2; j = i - n2 - n1;  idx = lvl0; }
    else return;
    int node = idx[j];
    bool tern = (third[node] >= 0);
    int slot = lvl * 2 + (tern ? 0 : 1);
    int pos = atomicAdd(&g_cnt[slot], 1);
    g_list[slot][pos] = j;
}

// ---------------- main HMMA level kernel ----------------
__global__ __launch_bounds__(NT, 1)
void level_mma_kernel(int lvl,
                      const int* __restrict__ lvl_idx,
                      const int* __restrict__ lc, const int* __restrict__ rc,
                      const int* __restrict__ tcld,
                      const int* __restrict__ opids,
                      const __nv_bfloat16* __restrict__ W1bTh, const __nv_bfloat16* __restrict__ W1bTl,
                      const __nv_bfloat16* __restrict__ W2bTh, const __nv_bfloat16* __restrict__ W2bTl,
                      const __nv_bfloat16* __restrict__ W1tTh, const __nv_bfloat16* __restrict__ W1tTl,
                      const __nv_bfloat16* __restrict__ W2tTh, const __nv_bfloat16* __restrict__ W2tTl,
                      const float* __restrict__ b1b, const float* __restrict__ b2b,
                      const float* __restrict__ b1t, const float* __restrict__ b2t,
                      const float* __restrict__ gma, const float* __restrict__ bta,
                      float* __restrict__ final_out) {
    extern __shared__ char smem[];
    int nbt = gridDim.x >> 1;
    int tern = (blockIdx.x < (unsigned)nbt) ? 1 : 0;
    int slot = lvl * 2 + (tern ? 0 : 1);
    int cnt = g_cnt[slot];
    int blk = tern ? blockIdx.x : (blockIdx.x - nbt);
    int base = blk * MROWS;
    if (base >= cnt) return;

    const int K1 = tern ? 1024 : 768;
    const __nv_bfloat16* W1Th = tern ? W1tTh : W1bTh;
    const __nv_bfloat16* W1Tl = tern ? W1tTl : W1bTl;
    const __nv_bfloat16* W2Th = tern ? W2tTh : W2bTh;
    const __nv_bfloat16* W2Tl = tern ? W2tTl : W2bTl;
    const float* b1 = tern ? b1t : b1b;
    const float* b2 = tern ? b2t : b2b;

    int t = threadIdx.x;
    int lane = t & 31, wid = t >> 5;
    uint32_t sb = (uint32_t)__cvta_generic_to_shared(smem);

    uint64_t* sm_ptrh = (uint64_t*)(smem + OFF_PTRH);
    uint64_t* sm_ptrl = (uint64_t*)(smem + OFF_PTRL);
    uint64_t* sm_ptrf = (uint64_t*)(smem + OFF_PTRF);
    int* sm_node  = (int*)(smem + OFF_NODE);
    int* sm_idx   = (int*)(smem + OFF_IDX);
    int* sm_valid = (int*)(smem + OFF_VALID);
    float* sm_mu  = (float*)(smem + OFF_MU);
    float* sm_rs  = (float*)(smem + OFF_RS);

    const int* rows = g_list[slot];
    if (t < MROWS) {
        int rr = min(base + t, cnt - 1);
        int i = rows[rr];
        int node = lvl_idx[i];
        sm_node[t] = node;
        sm_idx[t] = i;
        sm_valid[t] = (base + t < cnt) ? 1 : 0;
        size_t oo = (size_t)opids[node] * D;
        size_t lo_ = (size_t)lc[node] * D;
        size_t ro_ = (size_t)rc[node] * D;
        size_t to_ = tern ? (size_t)tcld[node] * D : lo_;
        sm_ptrh[t * 4 + 0] = (uint64_t)(g_oph + oo);
        sm_ptrh[t * 4 + 1] = (uint64_t)(g_embh + lo_);
        sm_ptrh[t * 4 + 2] = (uint64_t)(g_embh + ro_);
        sm_ptrh[t * 4 + 3] = (uint64_t)(g_embh + to_);
        sm_ptrl[t * 4 + 0] = (uint64_t)(g_opl + oo);
        sm_ptrl[t * 4 + 1] = (uint64_t)(g_embl + lo_);
        sm_ptrl[t * 4 + 2] = (uint64_t)(g_embl + ro_);
        sm_ptrl[t * 4 + 3] = (uint64_t)(g_embl + to_);
        sm_ptrf[t * 4 + 1] = (uint64_t)(g_embeds + lo_);
        sm_ptrf[t * 4 + 2] = (uint64_t)(g_embeds + ro_);
        sm_ptrf[t * 4 + 3] = (uint64_t)(g_embeds + to_);
    }
    __syncthreads();

    int wm = wid & 1, wn = wid >> 1;
    int m0 = wm * 32;
    int laneA_row  = lane & 15;
    int laneA_koff = (lane >> 4) * 16;
    int laneB_nrow = (lane & 7) + ((lane & 16) >> 1);
    int laneB_koff = ((lane >> 3) & 1) * 16;

    // per-thread load indices (fixed)
    int a_row = t >> 2, a_q = t & 3;         // A1 gather
    int b_r = t >> 1, b_half = t & 1;        // B1 load

    float c2[2][8][4];
    #pragma unroll
    for (int i = 0; i < 2; i++)
        #pragma unroll
        for (int j = 0; j < 8; j++)
            #pragma unroll
            for (int r = 0; r < 4; r++) c2[i][j][r] = 0.0f;

    int nkc = K1 >> 6;

    for (int ph = 0; ph < 4; ph++) {
        float c1[2][4][4];
        #pragma unroll
        for (int i = 0; i < 2; i++)
            #pragma unroll
            for (int j = 0; j < 4; j++)
                #pragma unroll
                for (int r = 0; r < 4; r++) c1[i][j][r] = 0.0f;

        // ---- GEMM1 with double-buffered cp.async ----
        // issue chunk 0
        {
            int k0 = 0, seg = 0, soffB = a_q * 32;
            const char* srcH = (const char*)((const __nv_bfloat16*)sm_ptrh[a_row * 4 + seg]) + soffB;
            const char* srcL = (const char*)((const __nv_bfloat16*)sm_ptrl[a_row * 4 + seg]) + soffB;
            uint32_t dH = sb + PA1H_(0) + a_row * 144 + a_q * 32;
            uint32_t dL = sb + PA1L_(0) + a_row * 144 + a_q * 32;
            cpasync16(dH, srcH); cpasync16(dH + 16, srcH + 16);
            cpasync16(dL, srcL); cpasync16(dL + 16, srcL + 16);
            const char* wsH = (const char*)(W1Th + (size_t)(ph * 128 + b_r) * K1 + k0 + b_half * 32);
            const char* wsL = (const char*)(W1Tl + (size_t)(ph * 128 + b_r) * K1 + k0 + b_half * 32);
            uint32_t eH = sb + PB1H_(0) + b_r * 144 + b_half * 64;
            uint32_t eL = sb + PB1L_(0) + b_r * 144 + b_half * 64;
            #pragma unroll
            for (int j = 0; j < 4; j++) cpasync16(eH + j * 16, wsH + j * 16);
            #pragma unroll
            for (int j = 0; j < 4; j++) cpasync16(eL + j * 16, wsL + j * 16);
            CP_COMMIT();
        }
        for (int kc = 0; kc < nkc; kc++) {
            CP_WAIT0();
            __syncthreads();
            if (kc + 1 < nkc) {
                int buf = (kc + 1) & 1;
                int k0 = (kc + 1) * 64, seg = k0 >> 8;
                int soffB = ((k0 & 255) + a_q * 16) * 2;
                const char* srcH = (const char*)((const __nv_bfloat16*)sm_ptrh[a_row * 4 + seg]) + soffB;
                const char* srcL = (const char*)((const __nv_bfloat16*)sm_ptrl[a_row * 4 + seg]) + soffB;
                uint32_t dH = sb + PA1H_(buf) + a_row * 144 + a_q * 32;
                uint32_t dL = sb + PA1L_(buf) + a_row * 144 + a_q * 32;
                cpasync16(dH, srcH); cpasync16(dH + 16, srcH + 16);
                cpasync16(dL, srcL); cpasync16(dL + 16, srcL + 16);
                const char* wsH = (const char*)(W1Th + (size_t)(ph * 128 + b_r) * K1 + k0 + b_half * 32);
                const char* wsL = (const char*)(W1Tl + (size_t)(ph * 128 + b_r) * K1 + k0 + b_half * 32);
                uint32_t eH = sb + PB1H_(buf) + b_r * 144 + b_half * 64;
                uint32_t eL = sb + PB1L_(buf) + b_r * 144 + b_half * 64;
                #pragma unroll
                for (int j = 0; j < 4; j++) cpasync16(eH + j * 16, wsH + j * 16);
                #pragma unroll
                for (int j = 0; j < 4; j++) cpasync16(eL + j * 16, wsL + j * 16);
                CP_COMMIT();
            }
            int buf = kc & 1;
            uint32_t AH = PA1H_(buf), AL = PA1L_(buf), BH = PB1H_(buf), BL = PB1L_(buf);
            int n0 = wn * 32;
            #pragma unroll
            for (int ks = 0; ks < 4; ks++) {
                int kb = ks * 32;
                uint32_t a0[4], a1[4], bh0[4], bh1[4], bl0[4], bl1[4];
                ldsm4(a0, sb + AH + (m0 + laneA_row) * 144 + kb + laneA_koff);
                ldsm4(a1, sb + AH + (m0 + 16 + laneA_row) * 144 + kb + laneA_koff);
                ldsm4(bh0, sb + BH + (n0 + laneB_nrow) * 144 + kb + laneB_koff);
                ldsm4(bh1, sb + BH + (n0 + 16 + laneB_nrow) * 144 + kb + laneB_koff);
                ldsm4(bl0, sb + BL + (n0 + laneB_nrow) * 144 + kb + laneB_koff);
                ldsm4(bl1, sb + BL + (n0 + 16 + laneB_nrow) * 144 + kb + laneB_koff);
                // Ah x Bh
                mma16816(c1[0][0], a0, bh0[0], bh0[1]); mma16816(c1[0][1], a0, bh0[2], bh0[3]);
                mma16816(c1[0][2], a0, bh1[0], bh1[1]); mma16816(c1[0][3], a0, bh1[2], bh1[3]);
                mma16816(c1[1][0], a1, bh0[0], bh0[1]); mma16816(c1[1][1], a1, bh0[2], bh0[3]);
                mma16816(c1[1][2], a1, bh1[0], bh1[1]); mma16816(c1[1][3], a1, bh1[2], bh1[3]);
                // Ah x Bl
                mma16816(c1[0][0], a0, bl0[0], bl0[1]); mma16816(c1[0][1], a0, bl0[2], bl0[3]);
                mma16816(c1[0][2], a0, bl1[0], bl1[1]); mma16816(c1[0][3], a0, bl1[2], bl1[3]);
                mma16816(c1[1][0], a1, bl0[0], bl0[1]); mma16816(c1[1][1], a1, bl0[2], bl0[3]);
                mma16816(c1[1][2], a1, bl1[0], bl1[1]); mma16816(c1[1][3], a1, bl1[2], bl1[3]);
                // Al x Bh
                ldsm4(a0, sb + AL + (m0 + laneA_row) * 144 + kb + laneA_koff);
                ldsm4(a1, sb + AL + (m0 + 16 + laneA_row) * 144 + kb + laneA_koff);
                mma16816(c1[0][0], a0, bh0[0], bh0[1]); mma16816(c1[0][1], a0, bh0[2], bh0[3]);
                mma16816(c1[0][2], a0, bh1[0], bh1[1]); mma16816(c1[0][3], a0, bh1[2], bh1[3]);
                mma16816(c1[1][0], a1, bh0[0], bh0[1]); mma16816(c1[1][1], a1, bh0[2], bh0[3]);
                mma16816(c1[1][2], a1, bh1[0], bh1[1]); mma16816(c1[1][3], a1, bh1[2], bh1[3]);
            }
        }

        // ---- GELU -> A2 tiles ----
        {
            int n0 = wn * 32;
            #pragma unroll
            for (int j = 0; j < 4; j++) {
                int ncol = n0 + j * 8 + (lane & 3) * 2;
                float2 bb = *(const float2*)(b1 + ph * 128 + ncol);
                #pragma unroll
                for (int i = 0; i < 2; i++) {
                    int mt = m0 + i * 16 + (lane >> 2);
                    float h0 = gelu_exact(c1[i][j][0] + bb.x);
                    float h1 = gelu_exact(c1[i][j][1] + bb.y);
                    *(uint32_t*)(smem + PA2H + mt * 272 + ncol * 2) = bfpack(h0, h1);
                    *(uint32_t*)(smem + PA2L + mt * 272 + ncol * 2) = bfpack(bfres(h0), bfres(h1));
                    float h2 = gelu_exact(c1[i][j][2] + bb.x);
                    float h3 = gelu_exact(c1[i][j][3] + bb.y);
                    *(uint32_t*)(smem + PA2H + (mt + 8) * 272 + ncol * 2) = bfpack(h2, h3);
                    *(uint32_t*)(smem + PA2L + (mt + 8) * 272 + ncol * 2) = bfpack(bfres(h2), bfres(h3));
                }
            }
        }
        __syncthreads();

        // ---- GEMM2 with double-buffered B2 ----
        {
            const char* wsH = (const char*)(W2Th + (size_t)t * HH + ph * 128);
            const char* wsL = (const char*)(W2Tl + (size_t)t * HH + ph * 128);
            uint32_t eH = sb + PB2H_(0) + t * 80;
            uint32_t eL = sb + PB2L_(0) + t * 80;
            #pragma unroll
            for (int j = 0; j < 4; j++) cpasync16(eH + j * 16, wsH + j * 16);
            #pragma unroll
            for (int j = 0; j < 4; j++) cpasync16(eL + j * 16, wsL + j * 16);
            CP_COMMIT();
        }
        for (int kc2 = 0; kc2 < 4; kc2++) {
            CP_WAIT0();
            __syncthreads();
            if (kc2 + 1 < 4) {
                int buf = (kc2 + 1) & 1;
                const char* wsH = (const char*)(W2Th + (size_t)t * HH + ph * 128 + (kc2 + 1) * 32);
                const char* wsL = (const char*)(W2Tl + (size_t)t * HH + ph * 128 + (kc2 + 1) * 32);
                uint32_t eH = sb + PB2H_(buf) + t * 80;
                uint32_t eL = sb + PB2L_(buf) + t * 80;
                #pragma unroll
                for (int j = 0; j < 4; j++) cpasync16(eH + j * 16, wsH + j * 16);
                #pragma unroll
                for (int j = 0; j < 4; j++) cpasync16(eL + j * 16, wsL + j * 16);
                CP_COMMIT();
            }
            int buf = kc2 & 1;
            uint32_t BH = PB2H_(buf), BL = PB2L_(buf);
            int n0 = wn * 64;
            #pragma unroll
            for (int ks = 0; ks < 2; ks++) {
                int kbA = kc2 * 64 + ks * 32;
                int kbB = ks * 32;
                uint32_t ah0[4], ah1[4], al0[4], al1[4];
                ldsm4(ah0, sb + PA2H + (m0 + laneA_row) * 272 + kbA + laneA_koff);
                ldsm4(ah1, sb + PA2H + (m0 + 16 + laneA_row) * 272 + kbA + laneA_koff);
                ldsm4(al0, sb + PA2L + (m0 + laneA_row) * 272 + kbA + laneA_koff);
                ldsm4(al1, sb + PA2L + (m0 + 16 + laneA_row) * 272 + kbA + laneA_koff);
                #pragma unroll
                for (int jj = 0; jj < 4; jj++) {
                    uint32_t bh[4], bl[4];
                    ldsm4(bh, sb + BH + (n0 + jj * 16 + laneB_nrow) * 80 + kbB + laneB_koff);
                    ldsm4(bl, sb + BL + (n0 + jj * 16 + laneB_nrow) * 80 + kbB + laneB_koff);
                    mma16816(c2[0][jj * 2],     ah0, bh[0], bh[1]);
                    mma16816(c2[0][jj * 2 + 1], ah0, bh[2], bh[3]);
                    mma16816(c2[1][jj * 2],     ah1, bh[0], bh[1]);
                    mma16816(c2[1][jj * 2 + 1], ah1, bh[2], bh[3]);
                    mma16816(c2[0][jj * 2],     ah0, bl[0], bl[1]);
                    mma16816(c2[0][jj * 2 + 1], ah0, bl[2], bl[3]);
                    mma16816(c2[1][jj * 2],     ah1, bl[0], bl[1]);
                    mma16816(c2[1][jj * 2 + 1], ah1, bl[2], bl[3]);
                    mma16816(c2[0][jj * 2],     al0, bh[0], bh[1]);
                    mma16816(c2[0][jj * 2 + 1], al0, bh[2], bh[3]);
                    mma16816(c2[1][jj * 2],     al1, bh[0], bh[1]);
                    mma16816(c2[1][jj * 2 + 1], al1, bh[2], bh[3]);
                }
            }
        }
        __syncthreads();   // pool reuse safe for next-phase GEMM1 / epilogue
    }

    // ---- epilogue: z = y + b2 + residual -> zbuf ----
    {
        int n0 = wn * 64;
        #pragma unroll
        for (int i = 0; i < 2; i++) {
            #pragma unroll
            for (int rh = 0; rh < 2; rh++) {
                int m = m0 + i * 16 + rh * 8 + (lane >> 2);
                const float* lp = (const float*)sm_ptrf[m * 4 + 1];
                const float* rp = (const float*)sm_ptrf[m * 4 + 2];
                const float* tp = (const float*)sm_ptrf[m * 4 + 3];
                #pragma unroll
                for (int j = 0; j < 8; j++) {
                    int n = n0 + j * 8 + (lane & 3) * 2;
                    float2 bv = *(const float2*)(b2 + n);
                    float y0 = c2[i][j][rh * 2]     + bv.x;
                    float y1 = c2[i][j][rh * 2 + 1] + bv.y;
                    float2 lv = *(const float2*)(lp + n);
                    float2 rv = *(const float2*)(rp + n);
                    if (tern) {
                        float2 tv = *(const float2*)(tp + n);
                        y0 += (lv.x + rv.x + tv.x) * (1.0f / 3.0f);
                        y1 += (lv.y + rv.y + tv.y) * (1.0f / 3.0f);
                    } else {
                        y0 += lv.x + rv.x;
                        y1 += lv.y + rv.y;
                    }
                    *(float2*)(smem + PZ + m * 1040 + n * 4) = make_float2(y0, y1);
                }
            }
        }
    }
    __syncthreads();

    if (t < MROWS) {
        const float* zr = (const float*)(smem + PZ + t * 1040);
        float s = 0.0f, s2 = 0.0f;
        #pragma unroll 8
        for (int c = 0; c < D; c++) {
            float v = zr[c];
            s += v;
            s2 += v * v;
        }
        float mu = s * (1.0f / 256.0f);
        float var = s2 * (1.0f / 256.0f) - mu * mu;
        sm_mu[t] = mu;
        sm_rs[t] = rsqrtf(var + 1e-5f);
    }
    __syncthreads();

    for (int idx = t; idx < MROWS * 64; idx += NT) {
        int row = idx >> 6, q = idx & 63;
        if (!sm_valid[row]) continue;
        float mu = sm_mu[row], rs = sm_rs[row];
        const float* zr = (const float*)(smem + PZ + row * 1040) + q * 4;
        float4 g4 = *(const float4*)(gma + q * 4);
        float4 be = *(const float4*)(bta + q * 4);
        float4 o;
        o.x = (zr[0] - mu) * rs * g4.x + be.x;
        o.y = (zr[1] - mu) * rs * g4.y + be.y;
        o.z = (zr[2] - mu) * rs * g4.z + be.z;
        o.w = (zr[3] - mu) * rs * g4.w + be.w;
        if (final_out) {
            *(float4*)(final_out + (size_t)sm_idx[row] * D + q * 4) = o;
        } else {
            size_t off = (size_t)sm_node[row] * D + q * 4;
            *(float4*)(g_embeds + off) = o;
            uint2 hv, lv;
            hv.x = bfpack(o.x, o.y);
            hv.y = bfpack(o.z, o.w);
            lv.x = bfpack(bfres(o.x), bfres(o.y));
            lv.y = bfpack(bfres(o.z), bfres(o.w));
            *(uint2*)(g_embh + off) = hv;
            *(uint2*)(g_embl + off) = lv;
        }
    }
}

// ---------------- launcher ----------------
extern "C" void kernel_launch(void* const* d_in, const int* in_sizes, int n_in,
                              void* d_out, int out_size) {
    const int*   comp_ids   = (const int*)d_in[0];
    const int*   op_ids     = (const int*)d_in[1];
    const int*   lc         = (const int*)d_in[2];
    const int*   rc         = (const int*)d_in[3];
    const int*   tc         = (const int*)d_in[4];
    const int*   l2         = (const int*)d_in[5];
    const int*   l1         = (const int*)d_in[6];
    const int*   l0         = (const int*)d_in[7];
    const float* comp_table = (const float*)d_in[8];
    const float* op_table   = (const float*)d_in[9];
    const float* W1b        = (const float*)d_in[10];
    const float* b1b        = (const float*)d_in[11];
    const float* W2b        = (const float*)d_in[12];
    const float* b2b        = (const float*)d_in[13];
    const float* W1t        = (const float*)d_in[14];
    const float* b1t        = (const float*)d_in[15];
    const float* W2t        = (const float*)d_in[16];
    const float* b2t        = (const float*)d_in[17];
    const float* gma        = (const float*)d_in[18];
    const float* bta        = (const float*)d_in[19];

    int n_nodes = in_sizes[0];
    int n2 = in_sizes[5], n1 = in_sizes[6], n0 = in_sizes[7];

    cudaFuncSetAttribute(level_mma_kernel, cudaFuncAttributeMaxDynamicSharedMemorySize,
                         SMEM_TOTAL);

    __nv_bfloat16 *w1bh, *w1bl, *w1th, *w1tl, *w2bh, *w2bl, *w2th, *w2tl;
    cudaGetSymbolAddress((void**)&w1bh, g_W1bTh);
    cudaGetSymbolAddress((void**)&w1bl, g_W1bTl);
    cudaGetSymbolAddress((void**)&w1th, g_W1tTh);
    cudaGetSymbolAddress((void**)&w1tl, g_W1tTl);
    cudaGetSymbolAddress((void**)&w2bh, g_W2bTh);
    cudaGetSymbolAddress((void**)&w2bl, g_W2bTl);
    cudaGetSymbolAddress((void**)&w2th, g_W2tTh);
    cudaGetSymbolAddress((void**)&w2tl, g_W2tTl);

    dim3 tb(32, 8);
    convall_kernel<<<1152, tb>>>(W1b, W1t, W2b, W2t);
    init_all_kernel<<<n_nodes + 16, D>>>(comp_ids, comp_table, op_table, n_nodes);
    int tot = n2 + n1 + n0;
    compact_kernel<<<(tot + 255) / 256, 256>>>(l2, n2, l1, n1, l0, n0, tc);

    int ns[3] = {n2, n1, n0};
    const int* lidx[3] = {l2, l1, l0};
    for (int lvl = 0; lvl < 3; lvl++) {
        int nb = (ns[lvl] + MROWS - 1) / MROWS;
        float* fout = (lvl == 2) ? (float*)d_out : nullptr;
        level_mma_kernel<<<2 * nb, NT, SMEM_TOTAL>>>(
            lvl, lidx[lvl], lc, rc, tc, op_ids,
            w1bh, w1bl, w2bh, w2bl, w1th, w1tl, w2th, w2tl,
            b1b, b2b, b1t, b2t, gma, bta, fout);
    }
}